// round 10
// baseline (speedup 1.0000x reference)
#include <cuda_runtime.h>
#include <cstdint>

#define N_NODES 16384
#define N_FEAT  16384
#define EMBED   64
#define BATCH   4096
#define N_EDGES 524288

#define MT     128
#define KT     32
#define NITR   (N_FEAT / KT)          // 512
#define ABYTES (MT * KT * 4)          // 16384
#define BBYTES (EMBED * KT * 4)       // 8192
#define STG    (ABYTES + BBYTES)      // 24576
#define NSTAGE 6
#define GEMM_SMEM (NSTAGE * STG)      // 147456

// ---------------- device scratch ----------------
__device__ int   g_is64;
__device__ int   g_degcnt[N_NODES];
__device__ int   g_need[N_NODES];
__device__ float g_dinv[N_NODES];
__device__ int   g_nsel;
__device__ int   g_sel_src[N_EDGES];
__device__ int   g_sel_dst[N_EDGES];
__device__ float g_sel_nrm[N_EDGES];
__device__ __align__(16) float g_wt[EMBED * N_FEAT];   // W^T, RNA-rounded to tf32
__device__ __align__(16) float g_xw[N_NODES * EMBED];
__device__ __align__(16) float g_agg[N_NODES * EMBED];

// ---------------- helpers ----------------
__device__ __forceinline__ uint32_t f2tf32(float f) {
    uint32_t r;
    asm("cvt.rna.tf32.f32 %0, %1;" : "=r"(r) : "f"(f));
    return r;
}
__device__ __forceinline__ int load_idx(const void* p, long long i, int is64) {
    if (is64) return (int)(((const long long*)p)[i]);
    return ((const int*)p)[i];
}
__device__ __forceinline__ void cp16(uint32_t dst, const void* src) {
    asm volatile("cp.async.cg.shared.global [%0], [%1], 16;" :: "r"(dst), "l"(src) : "memory");
}
__device__ __forceinline__ void cp_commit() {
    asm volatile("cp.async.commit_group;" ::: "memory");
}
__device__ __forceinline__ void cp_wait3() {
    asm volatile("cp.async.wait_group 3;" ::: "memory");
}
__device__ __forceinline__ uint32_t lds32(uint32_t a) {
    uint32_t v;
    asm volatile("ld.shared.b32 %0, [%1];" : "=r"(v) : "r"(a));
    return v;
}

#define MMA(d, a0, a1, a2, a3, b0, b1)                                          \
    asm volatile(                                                                \
        "mma.sync.aligned.m16n8k8.row.col.f32.tf32.tf32.f32 "                    \
        "{%0,%1,%2,%3}, {%4,%5,%6,%7}, {%8,%9}, {%0,%1,%2,%3};"                  \
        : "+f"((d)[0]), "+f"((d)[1]), "+f"((d)[2]), "+f"((d)[3])                 \
        : "r"(a0), "r"(a1), "r"(a2), "r"(a3), "r"(b0), "r"(b1))

// ---------------- small kernels ----------------
__global__ void k_detect(const void* __restrict__ x) {
    const long long* p = (const long long*)x;
    int lane = threadIdx.x;
    long long v0 = p[lane];
    long long v1 = p[lane + 32];
    int ok = (v0 >= 0 && v0 < N_NODES && v1 >= 0 && v1 < N_NODES);
    unsigned m = __ballot_sync(0xFFFFFFFFu, ok);
    if (lane == 0) g_is64 = (m == 0xFFFFFFFFu);
}
__global__ void k_zero() {
    int i = blockIdx.x * blockDim.x + threadIdx.x;
    g_degcnt[i] = 0;
    g_need[i] = 0;
    if (i == 0) g_nsel = 0;
}
__global__ void k_deg_mark(const void* __restrict__ edges, const void* __restrict__ x) {
    int t = blockIdx.x * blockDim.x + threadIdx.x;
    int is64 = g_is64;
    if (t < N_EDGES) {
        int dst = load_idx(edges, (long long)N_EDGES + t, is64);
        atomicAdd(&g_degcnt[dst], 1);
    } else {
        int i = load_idx(x, t - N_EDGES, is64);
        g_need[i] = 1;
    }
}
__global__ void k_dinv() {
    int i = blockIdx.x * blockDim.x + threadIdx.x;
    g_dinv[i] = rsqrtf(1.0f + (float)g_degcnt[i]);
}

// ---------------- W transpose (tiled, coalesced): g_wt[n][k] = tf32(W[k][n]) --
__global__ void __launch_bounds__(256) k_prep_wt(const float* __restrict__ W) {
    __shared__ float t[64][65];
    const int kb = blockIdx.x * 64;
    const int r = threadIdx.x >> 4;
    const int c = threadIdx.x & 15;
#pragma unroll
    for (int i = 0; i < 4; i++) {
        int row = r + 16 * i;
        float4 v = *(const float4*)(W + (long long)(kb + row) * EMBED + c * 4);
        t[row][c * 4 + 0] = v.x;
        t[row][c * 4 + 1] = v.y;
        t[row][c * 4 + 2] = v.z;
        t[row][c * 4 + 3] = v.w;
    }
    __syncthreads();
#pragma unroll
    for (int i = 0; i < 4; i++) {
        int n = r + 16 * i;
        float4 u;
        u.x = __uint_as_float(f2tf32(t[c * 4 + 0][n]));
        u.y = __uint_as_float(f2tf32(t[c * 4 + 1][n]));
        u.z = __uint_as_float(f2tf32(t[c * 4 + 2][n]));
        u.w = __uint_as_float(f2tf32(t[c * 4 + 3][n]));
        *(float4*)(g_wt + (long long)n * N_FEAT + kb + c * 4) = u;
    }
}

// ---------------- GEMM: g_xw = X @ W  (tf32 mma.sync) ----------------
// CTA 128x64 tile, 512 thr (16 warps = 4/SMSP), 1 CTA/SM.
// Warp wid: mq=wid&3 (32 rows), nh=(wid>>2)&1 (32 cols), kh=wid>>3 (k16 slice
// = 2 k8 steps of KT=32). 6-stage cp.async pipeline, ONE barrier/iter.
// 2-way kh merge in epilogue.
__global__ void __launch_bounds__(512, 1) k_gemm_mma(const float* __restrict__ X) {
    extern __shared__ __align__(16) char smem[];
    const uint32_t sb = (uint32_t)__cvta_generic_to_shared(smem);

    const int tid  = threadIdx.x;
    const int wid  = tid >> 5;
    const int lane = tid & 31;
    const int mq = wid & 3;
    const int nh = (wid >> 2) & 1;
    const int kh = wid >> 3;             // 0..1
    const int tf = lane >> 2;            // 0..7
    const int tk = lane & 3;             // 0..3
    const long long rb = (long long)blockIdx.x * MT;

    // ---- producer: thread copies 2 A chunks + 1 B chunk per stage
    const int q  = tid & 7;
    const int r0 = tid >> 3;             // 0..63
    const uint32_t dsw = (uint32_t)((q ^ (r0 & 7)) << 4);
    uint32_t adst[2], bdst;
    const float* asrc[2];
    const float* bsrc;
#pragma unroll
    for (int i = 0; i < 2; i++) {
        adst[i] = (uint32_t)((r0 + 64 * i) * 128) + dsw;
        asrc[i] = X + (rb + r0 + 64 * i) * (long long)N_FEAT + q * 4;
    }
    bdst = (uint32_t)(ABYTES + r0 * 128) + dsw;
    bsrc = g_wt + (long long)r0 * N_FEAT + q * 4;

    // ---- consumer offsets: ks=0,1 -> chunk c0 = 4*kh + 2*ks
    uint32_t ao[2][2], bo[4][2];
#pragma unroll
    for (int ks = 0; ks < 2; ks++) {
        const uint32_t csw = (uint32_t)((((4 * kh + 2 * ks)) ^ tf) << 4) + (uint32_t)(tk * 4);
#pragma unroll
        for (int mf = 0; mf < 2; mf++)
            ao[mf][ks] = (uint32_t)((mq * 32 + mf * 16 + tf) * 128) + csw;
#pragma unroll
        for (int nf = 0; nf < 4; nf++)
            bo[nf][ks] = (uint32_t)(ABYTES + (nh * 32 + nf * 8 + tf) * 128) + csw;
    }

    float acc[2][4][4] = {};

    // ---- prologue: commit tiles 0..4 (5 groups)
#pragma unroll
    for (int s = 0; s < NSTAGE - 1; s++) {
        const uint32_t st = sb + s * STG;
        const int ko = s * KT;
#pragma unroll
        for (int i = 0; i < 2; i++) cp16(st + adst[i], asrc[i] + ko);
        cp16(st + bdst, bsrc + ko);
        cp_commit();
    }
    cp_wait3();
    __syncthreads();

    // invariant at top of iter kt: tiles <= kt+1 landed & visible; slot
    // (kt+5)%6 (tile kt-1) fully consumed before the previous barrier.
    for (int kt = 0; kt < NITR; kt++) {
        // refill stage (kt+5)%6
        if (kt + NSTAGE - 1 < NITR) {
            const uint32_t st = sb + ((kt + NSTAGE - 1) % NSTAGE) * STG;
            const int ko = (kt + NSTAGE - 1) * KT;
#pragma unroll
            for (int i = 0; i < 2; i++) cp16(st + adst[i], asrc[i] + ko);
            cp16(st + bdst, bsrc + ko);
        }
        cp_commit();

        const uint32_t st = sb + (kt % NSTAGE) * STG;
#pragma unroll
        for (int ks = 0; ks < 2; ks++) {
            uint32_t b0[4], b1[4];
#pragma unroll
            for (int nf = 0; nf < 4; nf++) {
                b0[nf] = lds32(st + bo[nf][ks]);
                b1[nf] = lds32(st + (bo[nf][ks] ^ 16));
            }
#pragma unroll
            for (int mf = 0; mf < 2; mf++) {
                uint32_t a0 = f2tf32(__uint_as_float(lds32(st + ao[mf][ks])));
                uint32_t a1 = f2tf32(__uint_as_float(lds32(st + ao[mf][ks] + 1024)));
                uint32_t a2 = f2tf32(__uint_as_float(lds32(st + (ao[mf][ks] ^ 16))));
                uint32_t a3 = f2tf32(__uint_as_float(lds32(st + (ao[mf][ks] ^ 16) + 1024)));
#pragma unroll
                for (int nf = 0; nf < 4; nf++)
                    MMA(acc[mf][nf], a0, a1, a2, a3, b0[nf], b1[nf]);
            }
        }
        cp_wait3();
        __syncthreads();
    }

    // ---- epilogue: merge kh=1 partials into kh=0 warps (8 x 4KB regions)
    if (kh == 1) {
        float4* stp = (float4*)(smem + (wid - 8) * 4096);
#pragma unroll
        for (int mf = 0; mf < 2; mf++)
#pragma unroll
            for (int nf = 0; nf < 4; nf++)
                stp[(mf * 4 + nf) * 32 + lane] =
                    make_float4(acc[mf][nf][0], acc[mf][nf][1],
                                acc[mf][nf][2], acc[mf][nf][3]);
    }
    __syncthreads();
    if (kh == 0) {
        const float4* p0 = (const float4*)(smem + wid * 4096);
#pragma unroll
        for (int mf = 0; mf < 2; mf++) {
#pragma unroll
            for (int nf = 0; nf < 4; nf++) {
                const int o = (mf * 4 + nf) * 32 + lane;
                float4 u = p0[o];
                float c0 = acc[mf][nf][0] + u.x;
                float c1 = acc[mf][nf][1] + u.y;
                float c2 = acc[mf][nf][2] + u.z;
                float c3 = acc[mf][nf][3] + u.w;
                long long row = rb + mq * 32 + mf * 16 + tf;
                int col = nh * 32 + nf * 8 + 2 * tk;
                *(float2*)(g_xw + row * EMBED + col)       = make_float2(c0, c1);
                *(float2*)(g_xw + (row + 8) * EMBED + col) = make_float2(c2, c3);
            }
        }
    }
}

// ---------------- edge compaction: keep edges whose dst is referenced --------
__global__ void k_edge_sel(const void* __restrict__ edges) {
    int e = blockIdx.x * blockDim.x + threadIdx.x;
    int is64 = g_is64;
    int dst = load_idx(edges, (long long)N_EDGES + e, is64);
    if (!g_need[dst]) return;
    int src = load_idx(edges, e, is64);
    int pos = atomicAdd(&g_nsel, 1);
    g_sel_src[pos] = src;
    g_sel_dst[pos] = dst;
    g_sel_nrm[pos] = g_dinv[src] * g_dinv[dst];
}

// ---------------- aggregation init: self-loop term + bias ----------------
__global__ void k_agg_init(const float* __restrict__ b_gcn) {
    int i = blockIdx.x * blockDim.x + threadIdx.x;
    int n = i >> 6;
    int d = i & 63;
    float di = g_dinv[n];
    g_agg[i] = g_xw[i] * di * di + b_gcn[d];
}

// ---------------- edge aggregation (grid-stride over compacted list) ---------
__global__ void k_agg_edges() {
    const long long total = (long long)g_nsel * 16;
    const long long stride = (long long)gridDim.x * blockDim.x;
    for (long long t = (long long)blockIdx.x * blockDim.x + threadIdx.x;
         t < total; t += stride) {
        int e = (int)(t >> 4);
        int qd = (int)(t & 15);
        int src = g_sel_src[e];
        int dst = g_sel_dst[e];
        float nrm = g_sel_nrm[e];
        float4 v = ((const float4*)(g_xw + (long long)src * EMBED))[qd];
        float* o = g_agg + (long long)dst * EMBED + qd * 4;
        atomicAdd(o + 0, v.x * nrm);
        atomicAdd(o + 1, v.y * nrm);
        atomicAdd(o + 2, v.z * nrm);
        atomicAdd(o + 3, v.w * nrm);
    }
}

// ---------------- final head: lin + dot(emb0, emb1) ----------------
__global__ void k_final(const void* __restrict__ x,
                        const float* __restrict__ w_lin,
                        const float* __restrict__ b_lin,
                        float* __restrict__ out) {
    int b = blockIdx.x * (blockDim.x >> 5) + (threadIdx.x >> 5);
    int lane = threadIdx.x & 31;
    if (b >= BATCH) return;
    int is64 = g_is64;
    int i0 = load_idx(x, 2LL * b, is64);
    int i1 = load_idx(x, 2LL * b + 1, is64);
    const float* e0 = &g_agg[(long long)i0 * EMBED];
    const float* e1 = &g_agg[(long long)i1 * EMBED];
    float s = e0[lane] * e1[lane] + e0[lane + 32] * e1[lane + 32];
#pragma unroll
    for (int o = 16; o; o >>= 1) s += __shfl_xor_sync(0xFFFFFFFFu, s, o);
    if (lane == 0) out[b] = s + w_lin[i0] + w_lin[i1] + b_lin[0];
}

// ---------------- launch (GEMM kept 4th: the ncu-profiled slot) ---------------
extern "C" void kernel_launch(void* const* d_in, const int* in_sizes, int n_in,
                              void* d_out, int out_size) {
    const void*  x     = d_in[0];
    const float* X     = (const float*)d_in[1];
    const void*  edges = d_in[2];
    const float* Wg    = (const float*)d_in[3];
    const float* bg    = (const float*)d_in[4];
    const float* wl    = (const float*)d_in[5];
    const float* bl    = (const float*)d_in[6];
    float* out = (float*)d_out;

    cudaFuncSetAttribute(k_gemm_mma, cudaFuncAttributeMaxDynamicSharedMemorySize, GEMM_SMEM);

    k_detect<<<1, 32>>>(x);                                       // 1
    k_prep_wt<<<N_FEAT / 64, 256>>>(Wg);                          // 2
    k_zero<<<N_NODES / 256, 256>>>();                             // 3
    k_gemm_mma<<<N_NODES / MT, 512, GEMM_SMEM>>>(X);              // 4 <- profiled
    k_deg_mark<<<(N_EDGES + 2 * BATCH) / 256, 256>>>(edges, x);   // 5
    k_dinv<<<N_NODES / 256, 256>>>();                             // 6
    k_edge_sel<<<N_EDGES / 256, 256>>>(edges);                    // 7
    k_agg_init<<<(N_NODES * EMBED) / 256, 256>>>(bg);             // 8
    k_agg_edges<<<2048, 256>>>();                                 // 9
    k_final<<<BATCH / 8, 256>>>(x, wl, bl, out);                  // 10
}